// round 7
// baseline (speedup 1.0000x reference)
#include <cuda_runtime.h>
#include <cuda_bf16.h>

// Problem constants
#define HID   2048          // hidden
#define IMED  1408          // intermediate
#define TWOI  2816          // 2*I
#define NE    8             // experts
#define NTOK  8192          // B*S tokens
#define NPAIR 16384         // NTOK * top_k
#define PMAX  16896         // NPAIR + NE*64 padding headroom, multiple of 64
#define MTILES (PMAX/64)    // 264

// ---------------- device scratch (no allocations allowed) ----------------
__device__ int   g_counts[NE];
__device__ int   g_cursor[NE];
__device__ int   g_seg[NE + 1];
__device__ int   g_pair_token[PMAX];
__device__ int   g_slot[NPAIR];
__device__ float g_topw[NPAIR];
__device__ int   g_topi[NPAIR];
__device__ float g_yact[23789568];   // PMAX * IMED
__device__ float g_y2[34603008];     // PMAX * HID

// ---------------- init ----------------
__global__ void k_init() {
    int tid = blockIdx.x * blockDim.x + threadIdx.x;
    if (tid < NE) { g_counts[tid] = 0; g_cursor[tid] = 0; }
    for (int i = tid; i < PMAX; i += gridDim.x * blockDim.x)
        g_pair_token[i] = -1;
}

// ---------------- router: one warp per token ----------------
__global__ void k_router(const float* __restrict__ x, const float* __restrict__ rw) {
    int warp = (blockIdx.x * blockDim.x + threadIdx.x) >> 5;
    int lane = threadIdx.x & 31;
    if (warp >= NTOK) return;
    const float* xr = x + (size_t)warp * HID;
    float acc[NE];
#pragma unroll
    for (int e = 0; e < NE; e++) acc[e] = 0.0f;
    for (int h = lane; h < HID; h += 32) {
        float xv = xr[h];
#pragma unroll
        for (int e = 0; e < NE; e++)
            acc[e] = fmaf(xv, rw[e * HID + h], acc[e]);
    }
#pragma unroll
    for (int e = 0; e < NE; e++)
#pragma unroll
        for (int o = 16; o > 0; o >>= 1)
            acc[e] += __shfl_xor_sync(0xffffffffu, acc[e], o);
    if (lane == 0) {
        int i0 = 0; float v0 = acc[0];
#pragma unroll
        for (int e = 1; e < NE; e++) if (acc[e] > v0) { v0 = acc[e]; i0 = e; }
        int i1 = -1; float v1 = -3.402823466e38f;
#pragma unroll
        for (int e = 0; e < NE; e++) if (e != i0 && acc[e] > v1) { v1 = acc[e]; i1 = e; }
        float e1 = expf(v1 - v0);
        float inv = 1.0f / (1.0f + e1);
        g_topi[warp * 2 + 0] = i0;
        g_topi[warp * 2 + 1] = i1;
        g_topw[warp * 2 + 0] = inv;
        g_topw[warp * 2 + 1] = e1 * inv;
        atomicAdd(&g_counts[i0], 1);
        atomicAdd(&g_counts[i1], 1);
    }
}

// ---------------- 64-aligned segment offsets ----------------
__global__ void k_offsets() {
    if (threadIdx.x == 0) {
        int s = 0;
        for (int e = 0; e < NE; e++) {
            g_seg[e] = s;
            s += ((g_counts[e] + 63) >> 6) << 6;
        }
        g_seg[NE] = s;
    }
}

// ---------------- scatter pairs into expert segments ----------------
__global__ void k_scatter() {
    int t = blockIdx.x * blockDim.x + threadIdx.x;
    if (t >= NTOK) return;
#pragma unroll
    for (int k = 0; k < 2; k++) {
        int e = g_topi[t * 2 + k];
        int pos = g_seg[e] + atomicAdd(&g_cursor[e], 1);
        g_pair_token[pos] = t;
        g_slot[t * 2 + k] = pos;
    }
}

// ---------------- GEMM1 fused with SwiGLU ----------------
// C_gate[m,n] = sum_k x[tok_m,k]*w1[e, n, k];  C_up uses row n+1408.
// yact[m,n] = silu(gate)*up.  Tile 64(m) x 64(n) doing both halves.
__global__ __launch_bounds__(256, 2) void k_gemm1(const float* __restrict__ x,
                                                  const float* __restrict__ w1) {
    int row0 = blockIdx.x * 64;
    int total = g_seg[NE];
    if (row0 >= total) return;
    int e = 0;
#pragma unroll
    for (int i = 1; i < NE; i++) if (row0 >= g_seg[i]) e = i;
    int n0 = blockIdx.y * 64;
    const float* W = w1 + (size_t)e * TWOI * HID;

    __shared__ float As[16][64];
    __shared__ float Bg[16][64];
    __shared__ float Bu[16][64];

    int tid = threadIdx.x;
    int lr = tid >> 2;            // 0..63 (row of A / row of B tile to load)
    int kg = (tid & 3) << 2;      // 0,4,8,12 (k offset within BK=16)
    int tok = g_pair_token[row0 + lr];
    const float* ar  = (tok >= 0) ? (x + (size_t)tok * HID) : (const float*)0;
    const float* brg = W + (size_t)(n0 + lr) * HID;
    const float* bru = W + (size_t)(n0 + lr + IMED) * HID;

    int tx = tid & 15, ty = tid >> 4;
    float ag[4][4], au[4][4];
#pragma unroll
    for (int i = 0; i < 4; i++)
#pragma unroll
        for (int j = 0; j < 4; j++) { ag[i][j] = 0.0f; au[i][j] = 0.0f; }

    for (int k0 = 0; k0 < HID; k0 += 16) {
        float4 a4 = ar ? *(const float4*)(ar + k0 + kg) : make_float4(0.f, 0.f, 0.f, 0.f);
        float4 g4 = *(const float4*)(brg + k0 + kg);
        float4 u4 = *(const float4*)(bru + k0 + kg);
        __syncthreads();
        As[kg + 0][lr] = a4.x; As[kg + 1][lr] = a4.y; As[kg + 2][lr] = a4.z; As[kg + 3][lr] = a4.w;
        Bg[kg + 0][lr] = g4.x; Bg[kg + 1][lr] = g4.y; Bg[kg + 2][lr] = g4.z; Bg[kg + 3][lr] = g4.w;
        Bu[kg + 0][lr] = u4.x; Bu[kg + 1][lr] = u4.y; Bu[kg + 2][lr] = u4.z; Bu[kg + 3][lr] = u4.w;
        __syncthreads();
#pragma unroll
        for (int kk = 0; kk < 16; kk++) {
            float4 av = *(const float4*)&As[kk][ty << 2];
            float4 gv = *(const float4*)&Bg[kk][tx << 2];
            float4 uv = *(const float4*)&Bu[kk][tx << 2];
            float aa[4] = {av.x, av.y, av.z, av.w};
            float gg[4] = {gv.x, gv.y, gv.z, gv.w};
            float uu[4] = {uv.x, uv.y, uv.z, uv.w};
#pragma unroll
            for (int i = 0; i < 4; i++)
#pragma unroll
                for (int j = 0; j < 4; j++) {
                    ag[i][j] = fmaf(aa[i], gg[j], ag[i][j]);
                    au[i][j] = fmaf(aa[i], uu[j], au[i][j]);
                }
        }
    }
#pragma unroll
    for (int i = 0; i < 4; i++) {
        int m = row0 + (ty << 2) + i;
        float r[4];
#pragma unroll
        for (int j = 0; j < 4; j++) {
            float g = ag[i][j];
            float s = g / (1.0f + expf(-g));   // silu
            r[j] = s * au[i][j];
        }
        float4 o = make_float4(r[0], r[1], r[2], r[3]);
        *(float4*)&g_yact[(size_t)m * IMED + n0 + (tx << 2)] = o;
    }
}

// ---------------- GEMM2: y2[m,n] = sum_k yact[m,k] * w2[e, n, k] ----------------
__global__ __launch_bounds__(256, 2) void k_gemm2(const float* __restrict__ w2) {
    int row0 = blockIdx.x * 64;
    int total = g_seg[NE];
    if (row0 >= total) return;
    int e = 0;
#pragma unroll
    for (int i = 1; i < NE; i++) if (row0 >= g_seg[i]) e = i;
    int n0 = blockIdx.y * 64;
    const float* W = w2 + (size_t)e * HID * IMED;

    __shared__ float As[16][64];
    __shared__ float Bs[16][64];

    int tid = threadIdx.x;
    int lr = tid >> 2;
    int kg = (tid & 3) << 2;
    const float* ar = &g_yact[(size_t)(row0 + lr) * IMED];
    const float* br = W + (size_t)(n0 + lr) * IMED;

    int tx = tid & 15, ty = tid >> 4;
    float acc[4][4];
#pragma unroll
    for (int i = 0; i < 4; i++)
#pragma unroll
        for (int j = 0; j < 4; j++) acc[i][j] = 0.0f;

    for (int k0 = 0; k0 < IMED; k0 += 16) {
        float4 a4 = *(const float4*)(ar + k0 + kg);
        float4 b4 = *(const float4*)(br + k0 + kg);
        __syncthreads();
        As[kg + 0][lr] = a4.x; As[kg + 1][lr] = a4.y; As[kg + 2][lr] = a4.z; As[kg + 3][lr] = a4.w;
        Bs[kg + 0][lr] = b4.x; Bs[kg + 1][lr] = b4.y; Bs[kg + 2][lr] = b4.z; Bs[kg + 3][lr] = b4.w;
        __syncthreads();
#pragma unroll
        for (int kk = 0; kk < 16; kk++) {
            float4 av = *(const float4*)&As[kk][ty << 2];
            float4 bv = *(const float4*)&Bs[kk][tx << 2];
            float aa[4] = {av.x, av.y, av.z, av.w};
            float bb[4] = {bv.x, bv.y, bv.z, bv.w};
#pragma unroll
            for (int i = 0; i < 4; i++)
#pragma unroll
                for (int j = 0; j < 4; j++)
                    acc[i][j] = fmaf(aa[i], bb[j], acc[i][j]);
        }
    }
#pragma unroll
    for (int i = 0; i < 4; i++) {
        int m = row0 + (ty << 2) + i;
        float4 o = make_float4(acc[i][0], acc[i][1], acc[i][2], acc[i][3]);
        *(float4*)&g_y2[(size_t)m * HID + n0 + (tx << 2)] = o;
    }
}

// ---------------- combine: out[t] = w0*y2[slot0] + w1*y2[slot1] ----------------
__global__ void k_combine(float* __restrict__ out) {
    int gid = blockIdx.x * blockDim.x + threadIdx.x;   // NTOK * HID/4 threads
    if (gid >= NTOK * (HID / 4)) return;
    int t = gid >> 9;              // HID/4 = 512
    int c = (gid & 511) << 2;
    int s0 = g_slot[t * 2 + 0], s1 = g_slot[t * 2 + 1];
    float w0 = g_topw[t * 2 + 0], w1 = g_topw[t * 2 + 1];
    float4 a = *(const float4*)&g_y2[(size_t)s0 * HID + c];
    float4 b = *(const float4*)&g_y2[(size_t)s1 * HID + c];
    float4 o;
    o.x = w0 * a.x + w1 * b.x;
    o.y = w0 * a.y + w1 * b.y;
    o.z = w0 * a.z + w1 * b.z;
    o.w = w0 * a.w + w1 * b.w;
    *(float4*)(out + (size_t)gid * 4) = o;
}

// ---------------- launcher ----------------
extern "C" void kernel_launch(void* const* d_in, const int* in_sizes, int n_in,
                              void* d_out, int out_size) {
    const float* x  = (const float*)d_in[0];   // [4,2048,2048]
    const float* rw = (const float*)d_in[1];   // [8,2048]
    const float* w1 = (const float*)d_in[2];   // [8,2816,2048]
    const float* w2 = (const float*)d_in[3];   // [8,2048,1408]
    float* out = (float*)d_out;

    k_init<<<32, 256>>>();
    k_router<<<NTOK / 8, 256>>>(x, rw);        // 8 warps/block
    k_offsets<<<1, 32>>>();
    k_scatter<<<(NTOK + 255) / 256, 256>>>();

    dim3 g1(MTILES, IMED / 64);                // (264, 22)
    k_gemm1<<<g1, 256>>>(x, w1);

    dim3 g2(MTILES, HID / 64);                 // (264, 32)
    k_gemm2<<<g2, 256>>>(w2);

    k_combine<<<NTOK * (HID / 4) / 256, 256>>>(out);
}

// round 8
// speedup vs baseline: 1.1194x; 1.1194x over previous
#include <cuda_runtime.h>
#include <cuda_bf16.h>
#include <mma.h>

using namespace nvcuda;

// Problem constants
#define HID   2048          // hidden
#define IMED  1408          // intermediate
#define TWOI  2816          // 2*I
#define NE    8             // experts
#define NTOK  8192          // B*S tokens
#define NPAIR 16384         // NTOK * top_k
#define PMAX  17408         // NPAIR + NE*128 padding headroom, multiple of 128
#define MT128 (PMAX/128)    // 136

// ---------------- device scratch (no allocations allowed) ----------------
__device__ int   g_counts[NE];
__device__ int   g_cursor[NE];
__device__ int   g_seg[NE + 1];
__device__ int   g_pair_token[PMAX];
__device__ int   g_slot[NPAIR];
__device__ float g_topw[NPAIR];
__device__ int   g_topi[NPAIR];
__device__ float g_yact[24510464];   // PMAX * IMED
__device__ float g_y2[35651584];     // PMAX * HID

// ---------------- init ----------------
__global__ void k_init() {
    int tid = blockIdx.x * blockDim.x + threadIdx.x;
    if (tid < NE) { g_counts[tid] = 0; g_cursor[tid] = 0; }
    for (int i = tid; i < PMAX; i += gridDim.x * blockDim.x)
        g_pair_token[i] = -1;
}

// ---------------- router: one warp per token ----------------
__global__ void k_router(const float* __restrict__ x, const float* __restrict__ rw) {
    int warp = (blockIdx.x * blockDim.x + threadIdx.x) >> 5;
    int lane = threadIdx.x & 31;
    if (warp >= NTOK) return;
    const float* xr = x + (size_t)warp * HID;
    float acc[NE];
#pragma unroll
    for (int e = 0; e < NE; e++) acc[e] = 0.0f;
    for (int h = lane; h < HID; h += 32) {
        float xv = xr[h];
#pragma unroll
        for (int e = 0; e < NE; e++)
            acc[e] = fmaf(xv, rw[e * HID + h], acc[e]);
    }
#pragma unroll
    for (int e = 0; e < NE; e++)
#pragma unroll
        for (int o = 16; o > 0; o >>= 1)
            acc[e] += __shfl_xor_sync(0xffffffffu, acc[e], o);
    if (lane == 0) {
        int i0 = 0; float v0 = acc[0];
#pragma unroll
        for (int e = 1; e < NE; e++) if (acc[e] > v0) { v0 = acc[e]; i0 = e; }
        int i1 = -1; float v1 = -3.402823466e38f;
#pragma unroll
        for (int e = 0; e < NE; e++) if (e != i0 && acc[e] > v1) { v1 = acc[e]; i1 = e; }
        float e1 = expf(v1 - v0);
        float inv = 1.0f / (1.0f + e1);
        g_topi[warp * 2 + 0] = i0;
        g_topi[warp * 2 + 1] = i1;
        g_topw[warp * 2 + 0] = inv;
        g_topw[warp * 2 + 1] = e1 * inv;
        atomicAdd(&g_counts[i0], 1);
        atomicAdd(&g_counts[i1], 1);
    }
}

// ---------------- 128-aligned segment offsets ----------------
__global__ void k_offsets() {
    if (threadIdx.x == 0) {
        int s = 0;
        for (int e = 0; e < NE; e++) {
            g_seg[e] = s;
            s += ((g_counts[e] + 127) >> 7) << 7;
        }
        g_seg[NE] = s;
    }
}

// ---------------- scatter pairs into expert segments ----------------
__global__ void k_scatter() {
    int t = blockIdx.x * blockDim.x + threadIdx.x;
    if (t >= NTOK) return;
#pragma unroll
    for (int k = 0; k < 2; k++) {
        int e = g_topi[t * 2 + k];
        int pos = g_seg[e] + atomicAdd(&g_cursor[e], 1);
        g_pair_token[pos] = t;
        g_slot[t * 2 + k] = pos;
    }
}

// ============================================================================
// GEMM1 (tf32 wmma) fused with SwiGLU.
// CTA tile: 128(m) x 64(n of I). Computes gate cols [n0,n0+64) and up cols
// [n0+IMED, n0+IMED+64) simultaneously; epilogue writes silu(g)*u to g_yact.
// 8 warps: 2(m) x 4(n), warp tile 64x16 (4 m16n16k8 frags), K-chunk 32.
// ============================================================================
#define LDS 36   // smem leading dim (pad: 32 + 4), multiple of 4 floats

__global__ __launch_bounds__(256, 2) void k_gemm1(const float* __restrict__ x,
                                                  const float* __restrict__ w1) {
    int row0 = blockIdx.x * 128;
    int total = g_seg[NE];
    if (row0 >= total) return;
    int e = 0;
#pragma unroll
    for (int i = 1; i < NE; i++) if (row0 >= g_seg[i]) e = i;
    int n0 = blockIdx.y * 64;
    const float* W = w1 + (size_t)e * TWOI * HID;

    __shared__ float As[128][LDS];
    __shared__ float Bg[64][LDS];
    __shared__ float Bu[64][LDS];
    __shared__ int   toks[128];

    int tid = threadIdx.x;
    if (tid < 128) toks[tid] = g_pair_token[row0 + tid];
    __syncthreads();

    int warp = tid >> 5;
    int wm = warp >> 2;        // 0..1
    int wn = warp & 3;         // 0..3

    wmma::fragment<wmma::accumulator, 16, 16, 8, float> accG[4], accU[4];
#pragma unroll
    for (int i = 0; i < 4; i++) { wmma::fill_fragment(accG[i], 0.0f); wmma::fill_fragment(accU[i], 0.0f); }

    // loader indices: per float4
    int lrowA = tid >> 3;          // used as idx>>3 below
    (void)lrowA;

    for (int k0 = 0; k0 < HID; k0 += 32) {
        __syncthreads();
        // A: 128 rows x 32 k = 1024 float4, 4 per thread
#pragma unroll
        for (int it = 0; it < 4; it++) {
            int idx = tid + it * 256;
            int r = idx >> 3;
            int c4 = (idx & 7) << 2;
            int tok = toks[r];
            float4 v = make_float4(0.f, 0.f, 0.f, 0.f);
            if (tok >= 0) v = *(const float4*)(x + (size_t)tok * HID + k0 + c4);
            float4 o;
            o.x = wmma::__float_to_tf32(v.x); o.y = wmma::__float_to_tf32(v.y);
            o.z = wmma::__float_to_tf32(v.z); o.w = wmma::__float_to_tf32(v.w);
            *(float4*)&As[r][c4] = o;
        }
        // B gate + up: 64 rows x 32 k each = 512 float4 each, 2 per thread each
#pragma unroll
        for (int it = 0; it < 2; it++) {
            int idx = tid + it * 256;
            int r = idx >> 3;
            int c4 = (idx & 7) << 2;
            float4 v = *(const float4*)(W + (size_t)(n0 + r) * HID + k0 + c4);
            float4 o;
            o.x = wmma::__float_to_tf32(v.x); o.y = wmma::__float_to_tf32(v.y);
            o.z = wmma::__float_to_tf32(v.z); o.w = wmma::__float_to_tf32(v.w);
            *(float4*)&Bg[r][c4] = o;
            float4 u = *(const float4*)(W + (size_t)(n0 + r + IMED) * HID + k0 + c4);
            float4 ou;
            ou.x = wmma::__float_to_tf32(u.x); ou.y = wmma::__float_to_tf32(u.y);
            ou.z = wmma::__float_to_tf32(u.z); ou.w = wmma::__float_to_tf32(u.w);
            *(float4*)&Bu[r][c4] = ou;
        }
        __syncthreads();

#pragma unroll
        for (int kk = 0; kk < 32; kk += 8) {
            wmma::fragment<wmma::matrix_b, 16, 16, 8, wmma::precision::tf32, wmma::col_major> bg, bu;
            wmma::load_matrix_sync(bg, &Bg[wn * 16][kk], LDS);
            wmma::load_matrix_sync(bu, &Bu[wn * 16][kk], LDS);
#pragma unroll
            for (int i = 0; i < 4; i++) {
                wmma::fragment<wmma::matrix_a, 16, 16, 8, wmma::precision::tf32, wmma::row_major> a;
                wmma::load_matrix_sync(a, &As[wm * 64 + i * 16][kk], LDS);
                wmma::mma_sync(accG[i], a, bg, accG[i]);
                wmma::mma_sync(accU[i], a, bu, accU[i]);
            }
        }
    }

    // epilogue: silu(gate)*up, write to g_yact
#pragma unroll
    for (int i = 0; i < 4; i++) {
        wmma::fragment<wmma::accumulator, 16, 16, 8, float> res;
#pragma unroll
        for (int j = 0; j < res.num_elements; j++) {
            float g = accG[i].x[j];
            float s = g / (1.0f + expf(-g));
            res.x[j] = s * accU[i].x[j];
        }
        int m = row0 + wm * 64 + i * 16;
        int n = n0 + wn * 16;
        wmma::store_matrix_sync(&g_yact[(size_t)m * IMED + n], res, IMED, wmma::mem_row_major);
    }
}

// ============================================================================
// GEMM2 (tf32 wmma): y2[m,n] = sum_k yact[m,k] * w2[e, n, k]
// Same tiling: CTA 128x64, warp 64x16, K-chunk 32 (IMED=1408 -> 44 chunks)
// ============================================================================
__global__ __launch_bounds__(256, 2) void k_gemm2(const float* __restrict__ w2) {
    int row0 = blockIdx.x * 128;
    int total = g_seg[NE];
    if (row0 >= total) return;
    int e = 0;
#pragma unroll
    for (int i = 1; i < NE; i++) if (row0 >= g_seg[i]) e = i;
    int n0 = blockIdx.y * 64;
    const float* W = w2 + (size_t)e * HID * IMED;

    __shared__ float As[128][LDS];
    __shared__ float Bs[64][LDS];

    int tid = threadIdx.x;
    int warp = tid >> 5;
    int wm = warp >> 2;
    int wn = warp & 3;

    wmma::fragment<wmma::accumulator, 16, 16, 8, float> acc[4];
#pragma unroll
    for (int i = 0; i < 4; i++) wmma::fill_fragment(acc[i], 0.0f);

    for (int k0 = 0; k0 < IMED; k0 += 32) {
        __syncthreads();
#pragma unroll
        for (int it = 0; it < 4; it++) {
            int idx = tid + it * 256;
            int r = idx >> 3;
            int c4 = (idx & 7) << 2;
            float4 v = *(const float4*)&g_yact[(size_t)(row0 + r) * IMED + k0 + c4];
            float4 o;
            o.x = wmma::__float_to_tf32(v.x); o.y = wmma::__float_to_tf32(v.y);
            o.z = wmma::__float_to_tf32(v.z); o.w = wmma::__float_to_tf32(v.w);
            *(float4*)&As[r][c4] = o;
        }
#pragma unroll
        for (int it = 0; it < 2; it++) {
            int idx = tid + it * 256;
            int r = idx >> 3;
            int c4 = (idx & 7) << 2;
            float4 v = *(const float4*)(W + (size_t)(n0 + r) * IMED + k0 + c4);
            float4 o;
            o.x = wmma::__float_to_tf32(v.x); o.y = wmma::__float_to_tf32(v.y);
            o.z = wmma::__float_to_tf32(v.z); o.w = wmma::__float_to_tf32(v.w);
            *(float4*)&Bs[r][c4] = o;
        }
        __syncthreads();

#pragma unroll
        for (int kk = 0; kk < 32; kk += 8) {
            wmma::fragment<wmma::matrix_b, 16, 16, 8, wmma::precision::tf32, wmma::col_major> b;
            wmma::load_matrix_sync(b, &Bs[wn * 16][kk], LDS);
#pragma unroll
            for (int i = 0; i < 4; i++) {
                wmma::fragment<wmma::matrix_a, 16, 16, 8, wmma::precision::tf32, wmma::row_major> a;
                wmma::load_matrix_sync(a, &As[wm * 64 + i * 16][kk], LDS);
                wmma::mma_sync(acc[i], a, b, acc[i]);
            }
        }
    }

#pragma unroll
    for (int i = 0; i < 4; i++) {
        int m = row0 + wm * 64 + i * 16;
        int n = n0 + wn * 16;
        wmma::store_matrix_sync(&g_y2[(size_t)m * HID + n], acc[i], HID, wmma::mem_row_major);
    }
}

// ---------------- combine: out[t] = w0*y2[slot0] + w1*y2[slot1] ----------------
__global__ void k_combine(float* __restrict__ out) {
    int gid = blockIdx.x * blockDim.x + threadIdx.x;   // NTOK * HID/4 threads
    if (gid >= NTOK * (HID / 4)) return;
    int t = gid >> 9;              // HID/4 = 512
    int c = (gid & 511) << 2;
    int s0 = g_slot[t * 2 + 0], s1 = g_slot[t * 2 + 1];
    float w0 = g_topw[t * 2 + 0], w1 = g_topw[t * 2 + 1];
    float4 a = *(const float4*)&g_y2[(size_t)s0 * HID + c];
    float4 b = *(const float4*)&g_y2[(size_t)s1 * HID + c];
    float4 o;
    o.x = w0 * a.x + w1 * b.x;
    o.y = w0 * a.y + w1 * b.y;
    o.z = w0 * a.z + w1 * b.z;
    o.w = w0 * a.w + w1 * b.w;
    *(float4*)(out + (size_t)gid * 4) = o;
}

// ---------------- launcher ----------------
extern "C" void kernel_launch(void* const* d_in, const int* in_sizes, int n_in,
                              void* d_out, int out_size) {
    const float* x  = (const float*)d_in[0];   // [4,2048,2048]
    const float* rw = (const float*)d_in[1];   // [8,2048]
    const float* w1 = (const float*)d_in[2];   // [8,2816,2048]
    const float* w2 = (const float*)d_in[3];   // [8,2048,1408]
    float* out = (float*)d_out;

    k_init<<<32, 256>>>();
    k_router<<<NTOK / 8, 256>>>(x, rw);        // 8 warps/block
    k_offsets<<<1, 32>>>();
    k_scatter<<<(NTOK + 255) / 256, 256>>>();

    dim3 g1(MT128, IMED / 64);                 // (136, 22)
    k_gemm1<<<g1, 256>>>(x, w1);

    dim3 g2(MT128, HID / 64);                  // (136, 32)
    k_gemm2<<<g2, 256>>>(w2);

    k_combine<<<NTOK * (HID / 4) / 256, 256>>>(out);
}

// round 10
// speedup vs baseline: 2.0055x; 1.7917x over previous
#include <cuda_runtime.h>
#include <cuda_bf16.h>
#include <mma.h>

using namespace nvcuda;

// Problem constants
#define HID   2048          // hidden
#define IMED  1408          // intermediate
#define TWOI  2816          // 2*I
#define NE    8             // experts
#define NTOK  8192          // B*S tokens
#define NPAIR 16384         // NTOK * top_k
#define PMAX  17408         // NPAIR + NE*128 padding headroom, multiple of 128
#define MT128 (PMAX/128)    // 136

#define LDSW  36            // smem leading dim (32 + 4 pad)
#define SMEM_BYTES 73728    // dynamic smem per GEMM CTA

// ---------------- device scratch (no allocations allowed) ----------------
__device__ int   g_counts[NE];
__device__ int   g_cursor[NE];
__device__ int   g_seg[NE + 1];
__device__ int   g_pair_token[PMAX];
__device__ int   g_slot[NPAIR];
__device__ float g_topw[NPAIR];
__device__ int   g_topi[NPAIR];
__device__ float g_yact[24510464];   // PMAX * IMED  (stored pre-rounded to tf32)
__device__ float g_y2[35651584];     // PMAX * HID

// ---------------- init ----------------
__global__ void k_init() {
    int tid = blockIdx.x * blockDim.x + threadIdx.x;
    if (tid < NE) { g_counts[tid] = 0; g_cursor[tid] = 0; }
    for (int i = tid; i < PMAX; i += gridDim.x * blockDim.x)
        g_pair_token[i] = -1;
}

// ---------------- router: one warp per token ----------------
__global__ void k_router(const float* __restrict__ x, const float* __restrict__ rw) {
    int warp = (blockIdx.x * blockDim.x + threadIdx.x) >> 5;
    int lane = threadIdx.x & 31;
    if (warp >= NTOK) return;
    const float* xr = x + (size_t)warp * HID;
    float acc[NE];
#pragma unroll
    for (int e = 0; e < NE; e++) acc[e] = 0.0f;
    for (int h = lane; h < HID; h += 32) {
        float xv = xr[h];
#pragma unroll
        for (int e = 0; e < NE; e++)
            acc[e] = fmaf(xv, rw[e * HID + h], acc[e]);
    }
#pragma unroll
    for (int e = 0; e < NE; e++)
#pragma unroll
        for (int o = 16; o > 0; o >>= 1)
            acc[e] += __shfl_xor_sync(0xffffffffu, acc[e], o);
    if (lane == 0) {
        int i0 = 0; float v0 = acc[0];
#pragma unroll
        for (int e = 1; e < NE; e++) if (acc[e] > v0) { v0 = acc[e]; i0 = e; }
        int i1 = -1; float v1 = -3.402823466e38f;
#pragma unroll
        for (int e = 0; e < NE; e++) if (e != i0 && acc[e] > v1) { v1 = acc[e]; i1 = e; }
        float e1 = expf(v1 - v0);
        float inv = 1.0f / (1.0f + e1);
        g_topi[warp * 2 + 0] = i0;
        g_topi[warp * 2 + 1] = i1;
        g_topw[warp * 2 + 0] = inv;
        g_topw[warp * 2 + 1] = e1 * inv;
        atomicAdd(&g_counts[i0], 1);
        atomicAdd(&g_counts[i1], 1);
    }
}

// ---------------- 128-aligned segment offsets ----------------
__global__ void k_offsets() {
    if (threadIdx.x == 0) {
        int s = 0;
        for (int e = 0; e < NE; e++) {
            g_seg[e] = s;
            s += ((g_counts[e] + 127) >> 7) << 7;
        }
        g_seg[NE] = s;
    }
}

// ---------------- scatter pairs into expert segments ----------------
__global__ void k_scatter() {
    int t = blockIdx.x * blockDim.x + threadIdx.x;
    if (t >= NTOK) return;
#pragma unroll
    for (int k = 0; k < 2; k++) {
        int e = g_topi[t * 2 + k];
        int pos = g_seg[e] + atomicAdd(&g_cursor[e], 1);
        g_pair_token[pos] = t;
        g_slot[t * 2 + k] = pos;
    }
}

__device__ __forceinline__ float4 tf32x4(float4 v) {
    float4 o;
    o.x = wmma::__float_to_tf32(v.x); o.y = wmma::__float_to_tf32(v.y);
    o.z = wmma::__float_to_tf32(v.z); o.w = wmma::__float_to_tf32(v.w);
    return o;
}

// ============================================================================
// GEMM1 (tf32 wmma) fused with SwiGLU.
// CTA tile: 128(m) x 64(n of I) — gate cols [n0,n0+64) + up cols [IMED+n0,...).
// 8 warps 2(m) x 4(n); warp tile 64m x 16I (dual accumulators gate/up).
// Double-buffered smem, register prefetch, one sync per 32-K chunk.
// ============================================================================
__global__ __launch_bounds__(256, 2) void k_gemm1(const float* __restrict__ x,
                                                  const float* __restrict__ w1) {
    extern __shared__ float sm[];
    float* sA  = sm;                 // 2 * 128 * LDSW = 9216 floats
    float* sBg = sm + 9216;          // 2 *  64 * LDSW = 4608
    float* sBu = sm + 13824;         // 4608
    __shared__ int toks[128];

    int row0 = blockIdx.x * 128;
    int total = g_seg[NE];
    if (row0 >= total) return;
    int e = 0;
#pragma unroll
    for (int i = 1; i < NE; i++) if (row0 >= g_seg[i]) e = i;
    int n0 = blockIdx.y * 64;
    const float* W = w1 + (size_t)e * TWOI * HID;

    int tid = threadIdx.x;
    if (tid < 128) toks[tid] = g_pair_token[row0 + tid];
    __syncthreads();

    int warp = tid >> 5;
    int wm = warp >> 2;        // 0..1
    int wn = warp & 3;         // 0..3
    int rA = tid >> 3;         // loader row base (0..31)
    int c4 = (tid & 7) << 2;   // k offset 0..28

    wmma::fragment<wmma::accumulator, 16, 16, 8, float> accG[4], accU[4];
#pragma unroll
    for (int i = 0; i < 4; i++) { wmma::fill_fragment(accG[i], 0.0f); wmma::fill_fragment(accU[i], 0.0f); }

    float4 va[4], vg[2], vu[2];

    auto ldg = [&](int k0) {
#pragma unroll
        for (int it = 0; it < 4; it++) {
            int tok = toks[rA + it * 32];
            va[it] = (tok >= 0) ? *(const float4*)(x + (size_t)tok * HID + k0 + c4)
                                : make_float4(0.f, 0.f, 0.f, 0.f);
        }
#pragma unroll
        for (int it = 0; it < 2; it++) {
            int r = rA + it * 32;
            vg[it] = *(const float4*)(W + (size_t)(n0 + r) * HID + k0 + c4);
            vu[it] = *(const float4*)(W + (size_t)(n0 + r + IMED) * HID + k0 + c4);
        }
    };
    auto sts = [&](int p) {
#pragma unroll
        for (int it = 0; it < 4; it++)
            *(float4*)&sA[p * 4608 + (rA + it * 32) * LDSW + c4] = tf32x4(va[it]);
#pragma unroll
        for (int it = 0; it < 2; it++) {
            *(float4*)&sBg[p * 2304 + (rA + it * 32) * LDSW + c4] = tf32x4(vg[it]);
            *(float4*)&sBu[p * 2304 + (rA + it * 32) * LDSW + c4] = tf32x4(vu[it]);
        }
    };
    auto compute = [&](int p) {
#pragma unroll
        for (int kk = 0; kk < 32; kk += 8) {
            wmma::fragment<wmma::matrix_b, 16, 16, 8, wmma::precision::tf32, wmma::col_major> bg, bu;
            wmma::load_matrix_sync(bg, &sBg[p * 2304 + (wn * 16) * LDSW + kk], LDSW);
            wmma::load_matrix_sync(bu, &sBu[p * 2304 + (wn * 16) * LDSW + kk], LDSW);
#pragma unroll
            for (int i = 0; i < 4; i++) {
                wmma::fragment<wmma::matrix_a, 16, 16, 8, wmma::precision::tf32, wmma::row_major> a;
                wmma::load_matrix_sync(a, &sA[p * 4608 + (wm * 64 + i * 16) * LDSW + kk], LDSW);
                wmma::mma_sync(accG[i], a, bg, accG[i]);
                wmma::mma_sync(accU[i], a, bu, accU[i]);
            }
        }
    };

    ldg(0);
    sts(0);
    __syncthreads();
    int p = 0;
    for (int k0 = 32; k0 < HID; k0 += 32) {
        ldg(k0);            // global loads for next chunk (in flight during compute)
        compute(p);
        sts(p ^ 1);
        __syncthreads();
        p ^= 1;
    }
    compute(p);

    // epilogue: silu(gate)*up -> g_yact (pre-rounded to tf32 for GEMM2's A path)
#pragma unroll
    for (int i = 0; i < 4; i++) {
        wmma::fragment<wmma::accumulator, 16, 16, 8, float> res;
#pragma unroll
        for (int j = 0; j < res.num_elements; j++) {
            float g = accG[i].x[j];
            float s = g / (1.0f + expf(-g));
            res.x[j] = wmma::__float_to_tf32(s * accU[i].x[j]);
        }
        int m = row0 + wm * 64 + i * 16;
        int n = n0 + wn * 16;
        wmma::store_matrix_sync(&g_yact[(size_t)m * IMED + n], res, IMED, wmma::mem_row_major);
    }
}

// ============================================================================
// GEMM2 (tf32 wmma): y2[m,n] = sum_k yact[m,k] * w2[e, n, k]
// CTA tile 128(m) x 128(n); 8 warps 2(m) x 4(n); warp tile 64 x 32.
// Double-buffered smem, register prefetch, one sync per 32-K chunk.
// ============================================================================
__global__ __launch_bounds__(256, 2) void k_gemm2(const float* __restrict__ w2) {
    extern __shared__ float sm[];
    float* sA = sm;            // 2 * 128 * LDSW = 9216 floats
    float* sB = sm + 9216;     // 9216

    int row0 = blockIdx.x * 128;
    int total = g_seg[NE];
    if (row0 >= total) return;
    int e = 0;
#pragma unroll
    for (int i = 1; i < NE; i++) if (row0 >= g_seg[i]) e = i;
    int n0 = blockIdx.y * 128;
    const float* W = w2 + (size_t)e * HID * IMED;

    int tid = threadIdx.x;
    int warp = tid >> 5;
    int wm = warp >> 2;        // 0..1  -> m offset wm*64
    int wn = warp & 3;         // 0..3  -> n offset wn*32
    int rA = tid >> 3;
    int c4 = (tid & 7) << 2;

    wmma::fragment<wmma::accumulator, 16, 16, 8, float> acc[4][2];
#pragma unroll
    for (int i = 0; i < 4; i++)
#pragma unroll
        for (int j = 0; j < 2; j++) wmma::fill_fragment(acc[i][j], 0.0f);

    float4 va[4], vb[4];

    auto ldg = [&](int k0) {
#pragma unroll
        for (int it = 0; it < 4; it++) {
            int r = rA + it * 32;
            va[it] = *(const float4*)&g_yact[(size_t)(row0 + r) * IMED + k0 + c4];
            vb[it] = *(const float4*)(W + (size_t)(n0 + r) * IMED + k0 + c4);
        }
    };
    auto sts = [&](int p) {
#pragma unroll
        for (int it = 0; it < 4; it++) {
            int r = rA + it * 32;
            *(float4*)&sA[p * 4608 + r * LDSW + c4] = va[it];          // yact pre-rounded
            *(float4*)&sB[p * 4608 + r * LDSW + c4] = tf32x4(vb[it]);
        }
    };
    auto compute = [&](int p) {
#pragma unroll
        for (int kk = 0; kk < 32; kk += 8) {
            wmma::fragment<wmma::matrix_b, 16, 16, 8, wmma::precision::tf32, wmma::col_major> b0, b1;
            wmma::load_matrix_sync(b0, &sB[p * 4608 + (wn * 32) * LDSW + kk], LDSW);
            wmma::load_matrix_sync(b1, &sB[p * 4608 + (wn * 32 + 16) * LDSW + kk], LDSW);
#pragma unroll
            for (int i = 0; i < 4; i++) {
                wmma::fragment<wmma::matrix_a, 16, 16, 8, wmma::precision::tf32, wmma::row_major> a;
                wmma::load_matrix_sync(a, &sA[p * 4608 + (wm * 64 + i * 16) * LDSW + kk], LDSW);
                wmma::mma_sync(acc[i][0], a, b0, acc[i][0]);
                wmma::mma_sync(acc[i][1], a, b1, acc[i][1]);
            }
        }
    };

    ldg(0);
    sts(0);
    __syncthreads();
    int p = 0;
    for (int k0 = 32; k0 < IMED; k0 += 32) {
        ldg(k0);
        compute(p);
        sts(p ^ 1);
        __syncthreads();
        p ^= 1;
    }
    compute(p);

#pragma unroll
    for (int i = 0; i < 4; i++)
#pragma unroll
        for (int j = 0; j < 2; j++) {
            int m = row0 + wm * 64 + i * 16;
            int n = n0 + wn * 32 + j * 16;
            wmma::store_matrix_sync(&g_y2[(size_t)m * HID + n], acc[i][j], HID, wmma::mem_row_major);
        }
}

// ---------------- combine: out[t] = w0*y2[slot0] + w1*y2[slot1] ----------------
__global__ void k_combine(float* __restrict__ out) {
    int gid = blockIdx.x * blockDim.x + threadIdx.x;   // NTOK * HID/4 threads
    if (gid >= NTOK * (HID / 4)) return;
    int t = gid >> 9;              // HID/4 = 512
    int c = (gid & 511) << 2;
    int s0 = g_slot[t * 2 + 0], s1 = g_slot[t * 2 + 1];
    float w0 = g_topw[t * 2 + 0], w1 = g_topw[t * 2 + 1];
    float4 a = *(const float4*)&g_y2[(size_t)s0 * HID + c];
    float4 b = *(const float4*)&g_y2[(size_t)s1 * HID + c];
    float4 o;
    o.x = w0 * a.x + w1 * b.x;
    o.y = w0 * a.y + w1 * b.y;
    o.z = w0 * a.z + w1 * b.z;
    o.w = w0 * a.w + w1 * b.w;
    *(float4*)(out + (size_t)gid * 4) = o;
}

// ---------------- launcher ----------------
extern "C" void kernel_launch(void* const* d_in, const int* in_sizes, int n_in,
                              void* d_out, int out_size) {
    const float* x  = (const float*)d_in[0];   // [4,2048,2048]
    const float* rw = (const float*)d_in[1];   // [8,2048]
    const float* w1 = (const float*)d_in[2];   // [8,2816,2048]
    const float* w2 = (const float*)d_in[3];   // [8,2048,1408]
    float* out = (float*)d_out;

    cudaFuncSetAttribute(k_gemm1, cudaFuncAttributeMaxDynamicSharedMemorySize, SMEM_BYTES);
    cudaFuncSetAttribute(k_gemm2, cudaFuncAttributeMaxDynamicSharedMemorySize, SMEM_BYTES);

    k_init<<<32, 256>>>();
    k_router<<<NTOK / 8, 256>>>(x, rw);        // 8 warps/block
    k_offsets<<<1, 32>>>();
    k_scatter<<<(NTOK + 255) / 256, 256>>>();

    dim3 g1(MT128, IMED / 64);                 // (136, 22)
    k_gemm1<<<g1, 256, SMEM_BYTES>>>(x, w1);

    dim3 g2(MT128, HID / 128);                 // (136, 16)
    k_gemm2<<<g2, 256, SMEM_BYTES>>>(w2);

    k_combine<<<NTOK * (HID / 4) / 256, 256>>>(out);
}

// round 13
// speedup vs baseline: 2.0174x; 1.0059x over previous
#include <cuda_runtime.h>
#include <cuda_bf16.h>
#include <cstdint>
#include <mma.h>

using namespace nvcuda;

// Problem constants
#define HID   2048          // hidden
#define IMED  1408          // intermediate
#define TWOI  2816          // 2*I
#define NE    8             // experts
#define NTOK  8192          // B*S tokens
#define NPAIR 16384         // NTOK * top_k
#define PMAX  17408         // NPAIR + NE*128 padding headroom, multiple of 128
#define MT128 (PMAX/128)    // 136

#define LDSW  36            // smem leading dim (32 + 4 pad)
#define SMEM_BYTES 73728    // dynamic smem per GEMM CTA

// ---------------- device scratch (no allocations allowed) ----------------
__device__ int   g_counts[NE];
__device__ int   g_cursor[NE];
__device__ int   g_seg[NE + 1];
__device__ int   g_pair_token[PMAX];
__device__ int   g_slot[NPAIR];
__device__ float g_topw[NPAIR];
__device__ int   g_topi[NPAIR];
__device__ float g_yact[24510464];   // PMAX * IMED  (stored pre-rounded to tf32)
__device__ float g_y2[35651584];     // PMAX * HID
__device__ float g_xr[16777216];     // NTOK * HID   x pre-rounded to tf32
__device__ float g_w1r[46137344];    // 8*2816*2048  w1 pre-rounded to tf32
__device__ float g_w2r[23068672];    // 8*2048*1408  w2 pre-rounded to tf32

// ---------------- cp.async helpers ----------------
__device__ __forceinline__ unsigned int smem_u32(const void* p) {
    return (unsigned int)__cvta_generic_to_shared(p);
}
#define CP16(dst, src, sz) \
    asm volatile("cp.async.cg.shared.global [%0], [%1], 16, %2;" :: "r"(dst), "l"(src), "r"(sz))
#define CP_COMMIT() asm volatile("cp.async.commit_group;" ::: "memory")
#define CP_WAIT0()  asm volatile("cp.async.wait_group 0;" ::: "memory")

__device__ __forceinline__ float4 tf32x4(float4 v) {
    float4 o;
    o.x = wmma::__float_to_tf32(v.x); o.y = wmma::__float_to_tf32(v.y);
    o.z = wmma::__float_to_tf32(v.z); o.w = wmma::__float_to_tf32(v.w);
    return o;
}

// ---------------- pre-round fp32 -> tf32 (RN) into scratch ----------------
__global__ void k_round(const float* __restrict__ src, float* __restrict__ dst, int n4) {
    int i = blockIdx.x * blockDim.x + threadIdx.x;
    if (i < n4) ((float4*)dst)[i] = tf32x4(((const float4*)src)[i]);
}

// ---------------- init ----------------
__global__ void k_init() {
    int tid = blockIdx.x * blockDim.x + threadIdx.x;
    if (tid < NE) { g_counts[tid] = 0; g_cursor[tid] = 0; }
    for (int i = tid; i < PMAX; i += gridDim.x * blockDim.x)
        g_pair_token[i] = -1;
}

// ---------------- router: one warp per token ----------------
__global__ void k_router(const float* __restrict__ x, const float* __restrict__ rw) {
    int warp = (blockIdx.x * blockDim.x + threadIdx.x) >> 5;
    int lane = threadIdx.x & 31;
    if (warp >= NTOK) return;
    const float* xr = x + (size_t)warp * HID;
    float acc[NE];
#pragma unroll
    for (int e = 0; e < NE; e++) acc[e] = 0.0f;
    for (int h = lane; h < HID; h += 32) {
        float xv = xr[h];
#pragma unroll
        for (int e = 0; e < NE; e++)
            acc[e] = fmaf(xv, rw[e * HID + h], acc[e]);
    }
#pragma unroll
    for (int e = 0; e < NE; e++)
#pragma unroll
        for (int o = 16; o > 0; o >>= 1)
            acc[e] += __shfl_xor_sync(0xffffffffu, acc[e], o);
    if (lane == 0) {
        int i0 = 0; float v0 = acc[0];
#pragma unroll
        for (int e = 1; e < NE; e++) if (acc[e] > v0) { v0 = acc[e]; i0 = e; }
        int i1 = -1; float v1 = -3.402823466e38f;
#pragma unroll
        for (int e = 0; e < NE; e++) if (e != i0 && acc[e] > v1) { v1 = acc[e]; i1 = e; }
        float e1 = expf(v1 - v0);
        float inv = 1.0f / (1.0f + e1);
        g_topi[warp * 2 + 0] = i0;
        g_topi[warp * 2 + 1] = i1;
        g_topw[warp * 2 + 0] = inv;
        g_topw[warp * 2 + 1] = e1 * inv;
        atomicAdd(&g_counts[i0], 1);
        atomicAdd(&g_counts[i1], 1);
    }
}

// ---------------- 128-aligned segment offsets ----------------
__global__ void k_offsets() {
    if (threadIdx.x == 0) {
        int s = 0;
        for (int e = 0; e < NE; e++) {
            g_seg[e] = s;
            s += ((g_counts[e] + 127) >> 7) << 7;
        }
        g_seg[NE] = s;
    }
}

// ---------------- scatter pairs into expert segments ----------------
__global__ void k_scatter() {
    int t = blockIdx.x * blockDim.x + threadIdx.x;
    if (t >= NTOK) return;
#pragma unroll
    for (int k = 0; k < 2; k++) {
        int e = g_topi[t * 2 + k];
        int pos = g_seg[e] + atomicAdd(&g_cursor[e], 1);
        g_pair_token[pos] = t;
        g_slot[t * 2 + k] = pos;
    }
}

// ============================================================================
// GEMM1 (tf32 wmma) fused with SwiGLU.
// CTA tile: 128(m) x 64(n of I) — gate cols [n0,n0+64) + up cols [IMED+n0,...).
// 8 warps 2(m) x 4(n); warp tile 64m x 16I (dual accumulators gate/up).
// cp.async 2-stage pipeline: all operands pre-rounded to tf32 in scratch.
// ============================================================================
__global__ __launch_bounds__(256, 2) void k_gemm1() {
    extern __shared__ float sm[];
    float* sA  = sm;                 // 2 * 128 * LDSW = 9216 floats
    float* sBg = sm + 9216;          // 2 *  64 * LDSW = 4608
    float* sBu = sm + 13824;         // 4608
    __shared__ int toks[128];

    int row0 = blockIdx.x * 128;
    int total = g_seg[NE];
    if (row0 >= total) return;
    int e = 0;
#pragma unroll
    for (int i = 1; i < NE; i++) if (row0 >= g_seg[i]) e = i;
    int n0 = blockIdx.y * 64;
    const float* W = g_w1r + (size_t)e * TWOI * HID;

    int tid = threadIdx.x;
    if (tid < 128) toks[tid] = g_pair_token[row0 + tid];
    __syncthreads();

    int warp = tid >> 5;
    int wm = warp >> 2;        // 0..1
    int wn = warp & 3;         // 0..3
    int rA = tid >> 3;         // loader row base (0..31)
    int c4 = (tid & 7) << 2;   // k offset 0..28

    unsigned int sAb  = smem_u32(sA);
    unsigned int sBgb = smem_u32(sBg);
    unsigned int sBub = smem_u32(sBu);

    // token row pointers for the 4 A rows this thread loads
    const float* aptr[4];
    int asz[4];
#pragma unroll
    for (int it = 0; it < 4; it++) {
        int tok = toks[rA + it * 32];
        aptr[it] = g_xr + (size_t)(tok >= 0 ? tok : 0) * HID + c4;
        asz[it] = (tok >= 0) ? 16 : 0;
    }

    wmma::fragment<wmma::accumulator, 16, 16, 8, float> accG[4], accU[4];
#pragma unroll
    for (int i = 0; i < 4; i++) { wmma::fill_fragment(accG[i], 0.0f); wmma::fill_fragment(accU[i], 0.0f); }

    auto issue = [&](int k0, int pp) {
#pragma unroll
        for (int it = 0; it < 4; it++) {
            int r = rA + it * 32;
            CP16(sAb + (unsigned int)(pp * 4608 + r * LDSW + c4) * 4u, aptr[it] + k0, asz[it]);
        }
#pragma unroll
        for (int it = 0; it < 2; it++) {
            int r = rA + it * 32;
            CP16(sBgb + (unsigned int)(pp * 2304 + r * LDSW + c4) * 4u,
                 W + (size_t)(n0 + r) * HID + k0 + c4, 16);
            CP16(sBub + (unsigned int)(pp * 2304 + r * LDSW + c4) * 4u,
                 W + (size_t)(n0 + r + IMED) * HID + k0 + c4, 16);
        }
        CP_COMMIT();
    };
    auto compute = [&](int pp) {
#pragma unroll
        for (int kk = 0; kk < 32; kk += 8) {
            wmma::fragment<wmma::matrix_b, 16, 16, 8, wmma::precision::tf32, wmma::col_major> bg, bu;
            wmma::load_matrix_sync(bg, &sBg[pp * 2304 + (wn * 16) * LDSW + kk], LDSW);
            wmma::load_matrix_sync(bu, &sBu[pp * 2304 + (wn * 16) * LDSW + kk], LDSW);
#pragma unroll
            for (int i = 0; i < 4; i++) {
                wmma::fragment<wmma::matrix_a, 16, 16, 8, wmma::precision::tf32, wmma::row_major> a;
                wmma::load_matrix_sync(a, &sA[pp * 4608 + (wm * 64 + i * 16) * LDSW + kk], LDSW);
                wmma::mma_sync(accG[i], a, bg, accG[i]);
                wmma::mma_sync(accU[i], a, bu, accU[i]);
            }
        }
    };

    issue(0, 0);
    int p = 0;
    for (int k0 = 32; k0 < HID; k0 += 32) {
        CP_WAIT0();
        __syncthreads();
        issue(k0, p ^ 1);      // async loads for next chunk land during compute
        compute(p);
        p ^= 1;
    }
    CP_WAIT0();
    __syncthreads();
    compute(p);

    // epilogue: silu(gate)*up -> g_yact (pre-rounded to tf32 for GEMM2's A path)
#pragma unroll
    for (int i = 0; i < 4; i++) {
        wmma::fragment<wmma::accumulator, 16, 16, 8, float> res;
#pragma unroll
        for (int j = 0; j < res.num_elements; j++) {
            float g = accG[i].x[j];
            float s = g / (1.0f + expf(-g));
            res.x[j] = wmma::__float_to_tf32(s * accU[i].x[j]);
        }
        int m = row0 + wm * 64 + i * 16;
        int n = n0 + wn * 16;
        wmma::store_matrix_sync(&g_yact[(size_t)m * IMED + n], res, IMED, wmma::mem_row_major);
    }
}

// ============================================================================
// GEMM2 (tf32 wmma): y2[m,n] = sum_k yact[m,k] * w2[e, n, k]
// CTA tile 128(m) x 128(n); 8 warps 2(m) x 4(n); warp tile 64 x 32.
// cp.async 2-stage pipeline; operands pre-rounded (yact in epilogue, w2 in scratch).
// ============================================================================
__global__ __launch_bounds__(256, 2) void k_gemm2() {
    extern __shared__ float sm[];
    float* sA = sm;            // 2 * 128 * LDSW = 9216 floats
    float* sB = sm + 9216;     // 9216

    int row0 = blockIdx.x * 128;
    int total = g_seg[NE];
    if (row0 >= total) return;
    int e = 0;
#pragma unroll
    for (int i = 1; i < NE; i++) if (row0 >= g_seg[i]) e = i;
    int n0 = blockIdx.y * 128;
    const float* W = g_w2r + (size_t)e * HID * IMED;

    int tid = threadIdx.x;
    int warp = tid >> 5;
    int wm = warp >> 2;        // 0..1  -> m offset wm*64
    int wn = warp & 3;         // 0..3  -> n offset wn*32
    int rA = tid >> 3;
    int c4 = (tid & 7) << 2;

    unsigned int sAb = smem_u32(sA);
    unsigned int sBb = smem_u32(sB);

    wmma::fragment<wmma::accumulator, 16, 16, 8, float> acc[4][2];
#pragma unroll
    for (int i = 0; i < 4; i++)
#pragma unroll
        for (int j = 0; j < 2; j++) wmma::fill_fragment(acc[i][j], 0.0f);

    auto issue = [&](int k0, int pp) {
#pragma unroll
        for (int it = 0; it < 4; it++) {
            int r = rA + it * 32;
            CP16(sAb + (unsigned int)(pp * 4608 + r * LDSW + c4) * 4u,
                 &g_yact[(size_t)(row0 + r) * IMED + k0 + c4], 16);
            CP16(sBb + (unsigned int)(pp * 4608 + r * LDSW + c4) * 4u,
                 W + (size_t)(n0 + r) * IMED + k0 + c4, 16);
        }
        CP_COMMIT();
    };
    auto compute = [&](int pp) {
#pragma unroll
        for (int kk = 0; kk < 32; kk += 8) {
            wmma::fragment<wmma::matrix_b, 16, 16, 8, wmma::precision::tf32, wmma::col_major> b0, b1;
            wmma::load_matrix_sync(b0, &sB[pp * 4608 + (wn * 32) * LDSW + kk], LDSW);
            wmma::load_matrix_sync(b1, &sB[pp * 4608 + (wn * 32 + 16) * LDSW + kk], LDSW);
#pragma unroll
            for (int i = 0; i < 4; i++) {
                wmma::fragment<wmma::matrix_a, 16, 16, 8, wmma::precision::tf32, wmma::row_major> a;
                wmma::load_matrix_sync(a, &sA[pp * 4608 + (wm * 64 + i * 16) * LDSW + kk], LDSW);
                wmma::mma_sync(acc[i][0], a, b0, acc[i][0]);
                wmma::mma_sync(acc[i][1], a, b1, acc[i][1]);
            }
        }
    };

    issue(0, 0);
    int p = 0;
    for (int k0 = 32; k0 < IMED; k0 += 32) {
        CP_WAIT0();
        __syncthreads();
        issue(k0, p ^ 1);
        compute(p);
        p ^= 1;
    }
    CP_WAIT0();
    __syncthreads();
    compute(p);

#pragma unroll
    for (int i = 0; i < 4; i++)
#pragma unroll
        for (int j = 0; j < 2; j++) {
            int m = row0 + wm * 64 + i * 16;
            int n = n0 + wn * 32 + j * 16;
            wmma::store_matrix_sync(&g_y2[(size_t)m * HID + n], acc[i][j], HID, wmma::mem_row_major);
        }
}

// ---------------- combine: out[t] = w0*y2[slot0] + w1*y2[slot1] ----------------
__global__ void k_combine(float* __restrict__ out) {
    int gid = blockIdx.x * blockDim.x + threadIdx.x;   // NTOK * HID/4 threads
    if (gid >= NTOK * (HID / 4)) return;
    int t = gid >> 9;              // HID/4 = 512
    int c = (gid & 511) << 2;
    int s0 = g_slot[t * 2 + 0], s1 = g_slot[t * 2 + 1];
    float w0 = g_topw[t * 2 + 0], w1 = g_topw[t * 2 + 1];
    float4 a = *(const float4*)&g_y2[(size_t)s0 * HID + c];
    float4 b = *(const float4*)&g_y2[(size_t)s1 * HID + c];
    float4 o;
    o.x = w0 * a.x + w1 * b.x;
    o.y = w0 * a.y + w1 * b.y;
    o.z = w0 * a.z + w1 * b.z;
    o.w = w0 * a.w + w1 * b.w;
    *(float4*)(out + (size_t)gid * 4) = o;
}

// ---------------- launcher ----------------
extern "C" void kernel_launch(void* const* d_in, const int* in_sizes, int n_in,
                              void* d_out, int out_size) {
    const float* x  = (const float*)d_in[0];   // [4,2048,2048]
    const float* rw = (const float*)d_in[1];   // [8,2048]
    const float* w1 = (const float*)d_in[2];   // [8,2816,2048]
    const float* w2 = (const float*)d_in[3];   // [8,2048,1408]
    float* out = (float*)d_out;

    cudaFuncSetAttribute(k_gemm1, cudaFuncAttributeMaxDynamicSharedMemorySize, SMEM_BYTES);
    cudaFuncSetAttribute(k_gemm2, cudaFuncAttributeMaxDynamicSharedMemorySize, SMEM_BYTES);

    k_init<<<32, 256>>>();
    k_router<<<NTOK / 8, 256>>>(x, rw);        // 8 warps/block

    // pre-round operands to tf32 (RN) into scratch
    float* d_xr, *d_w1r, *d_w2r;
    cudaGetSymbolAddress((void**)&d_xr,  g_xr);
    cudaGetSymbolAddress((void**)&d_w1r, g_w1r);
    cudaGetSymbolAddress((void**)&d_w2r, g_w2r);
    k_round<<<16384, 256>>>(x,  d_xr,  NTOK * HID / 4);
    k_round<<<45056, 256>>>(w1, d_w1r, NE * TWOI * HID / 4);
    k_round<<<22528, 256>>>(w2, d_w2r, NE * HID * IMED / 4);

    k_offsets<<<1, 32>>>();
    k_scatter<<<(NTOK + 255) / 256, 256>>>();

    dim3 g1(MT128, IMED / 64);                 // (136, 22)
    k_gemm1<<<g1, 256, SMEM_BYTES>>>();

    dim3 g2(MT128, HID / 128);                 // (136, 16)
    k_gemm2<<<g2, 256, SMEM_BYTES>>>();

    k_combine<<<NTOK * (HID / 4) / 256, 256>>>(out);
}

// round 17
// speedup vs baseline: 2.1463x; 1.0639x over previous
#include <cuda_runtime.h>
#include <cuda_bf16.h>
#include <cstdint>
#include <mma.h>

using namespace nvcuda;

// Problem constants
#define HID   2048
#define IMED  1408
#define TWOI  2816
#define NE    8
#define NTOK  8192
#define NPAIR 16384
#define PMAX  17408
#define MT128 (PMAX/128)    // 136

#define LDSW  36            // smem leading dim (32 + 4 pad)
#define DSMEM 110592        // dynamic smem: 27648 floats

// ---------------- device scratch ----------------
__device__ int   g_counts[NE];
__device__ int   g_cursor[NE];
__device__ int   g_seg[NE + 1];
__device__ int   g_pair_token[PMAX];
__device__ int   g_slot[NPAIR];
__device__ float g_topw[NPAIR];
__device__ int   g_topi[NPAIR];
__device__ float g_yact[24510464];   // PMAX * IMED (tf32-rounded)
__device__ float g_y2[35651584];     // PMAX * HID
__device__ float g_xr[16777216];     // x rounded to tf32
__device__ float g_w1r[46137344];    // w1 rounded
__device__ float g_w2r[23068672];    // w2 rounded

// ---------------- cp.async helpers ----------------
__device__ __forceinline__ unsigned smem_u32(const void* p) {
    return (unsigned)__cvta_generic_to_shared(p);
}
#define CP16(dst, src, sz) \
    asm volatile("cp.async.cg.shared.global [%0], [%1], 16, %2;" :: "r"(dst), "l"(src), "r"(sz))
#define CP_COMMIT() asm volatile("cp.async.commit_group;" ::: "memory")
#define CP_WAIT0()  asm volatile("cp.async.wait_group 0;" ::: "memory")

__device__ __forceinline__ float4 tf32x4(float4 v) {
    float4 o;
    o.x = wmma::__float_to_tf32(v.x); o.y = wmma::__float_to_tf32(v.y);
    o.z = wmma::__float_to_tf32(v.z); o.w = wmma::__float_to_tf32(v.w);
    return o;
}

// ---------------- pre-round fp32 -> tf32 (RN) ----------------
__global__ void k_round(const float* __restrict__ src, float* __restrict__ dst, int n4) {
    int i = blockIdx.x * blockDim.x + threadIdx.x;
    if (i < n4) ((float4*)dst)[i] = tf32x4(((const float4*)src)[i]);
}

// ---------------- init ----------------
__global__ void k_init() {
    int tid = blockIdx.x * blockDim.x + threadIdx.x;
    if (tid < NE) { g_counts[tid] = 0; g_cursor[tid] = 0; }
    for (int i = tid; i < PMAX; i += gridDim.x * blockDim.x)
        g_pair_token[i] = -1;
}

// ---------------- router ----------------
__global__ void k_router(const float* __restrict__ x, const float* __restrict__ rw) {
    int warp = (blockIdx.x * blockDim.x + threadIdx.x) >> 5;
    int lane = threadIdx.x & 31;
    if (warp >= NTOK) return;
    const float* xr = x + (size_t)warp * HID;
    float acc[NE];
#pragma unroll
    for (int e = 0; e < NE; e++) acc[e] = 0.0f;
    for (int h = lane; h < HID; h += 32) {
        float xv = xr[h];
#pragma unroll
        for (int e = 0; e < NE; e++)
            acc[e] = fmaf(xv, rw[e * HID + h], acc[e]);
    }
#pragma unroll
    for (int e = 0; e < NE; e++)
#pragma unroll
        for (int o = 16; o > 0; o >>= 1)
            acc[e] += __shfl_xor_sync(0xffffffffu, acc[e], o);
    if (lane == 0) {
        int i0 = 0; float v0 = acc[0];
#pragma unroll
        for (int e = 1; e < NE; e++) if (acc[e] > v0) { v0 = acc[e]; i0 = e; }
        int i1 = -1; float v1 = -3.402823466e38f;
#pragma unroll
        for (int e = 0; e < NE; e++) if (e != i0 && acc[e] > v1) { v1 = acc[e]; i1 = e; }
        float e1 = expf(v1 - v0);
        float inv = 1.0f / (1.0f + e1);
        g_topi[warp * 2 + 0] = i0;
        g_topi[warp * 2 + 1] = i1;
        g_topw[warp * 2 + 0] = inv;
        g_topw[warp * 2 + 1] = e1 * inv;
        atomicAdd(&g_counts[i0], 1);
        atomicAdd(&g_counts[i1], 1);
    }
}

__global__ void k_offsets() {
    if (threadIdx.x == 0) {
        int s = 0;
        for (int e = 0; e < NE; e++) {
            g_seg[e] = s;
            s += ((g_counts[e] + 127) >> 7) << 7;
        }
        g_seg[NE] = s;
    }
}

__global__ void k_scatter() {
    int t = blockIdx.x * blockDim.x + threadIdx.x;
    if (t >= NTOK) return;
#pragma unroll
    for (int k = 0; k < 2; k++) {
        int e = g_topi[t * 2 + k];
        int pos = g_seg[e] + atomicAdd(&g_cursor[e], 1);
        g_pair_token[pos] = t;
        g_slot[t * 2 + k] = pos;
    }
}

// ============================================================================
// GEMM1 (tf32 wmma) fused SwiGLU.
// CTA: 128m x 128 I-cols (gate + up). 8 warps 2m x 4n; warp tile 64m x 32I
// with dual gate/up accumulators (16 frags). cp.async 2-stage pipeline.
// 8 fragment loads per 16 mma_syncs = 0.5 loads/mma.
// ============================================================================
__global__ __launch_bounds__(256, 1) void k_gemm1() {
    extern __shared__ float sm[];
    float* sA  = sm;            // 2 * 128 * LDSW = 9216 floats
    float* sBg = sm + 9216;     // 9216
    float* sBu = sm + 18432;    // 9216
    __shared__ int toks[128];

    int row0 = blockIdx.x * 128;
    if (row0 >= g_seg[NE]) return;
    int e = 0;
#pragma unroll
    for (int i = 1; i < NE; i++) if (row0 >= g_seg[i]) e = i;
    int n0 = blockIdx.y * 128;      // I-col base
    const float* W = g_w1r + (size_t)e * TWOI * HID;

    int tid = threadIdx.x;
    if (tid < 128) toks[tid] = g_pair_token[row0 + tid];
    __syncthreads();

    int warp = tid >> 5;
    int wm = warp >> 2;            // 0..1 -> m offset wm*64
    int wn = warp & 3;             // 0..3 -> I offset wn*32

    unsigned sAb  = smem_u32(sA);
    unsigned sBgb = smem_u32(sBg);
    unsigned sBub = smem_u32(sBu);

    // loader slots: A 1024 units (4/thread), Bg 1024 (4/thread), Bu 1024 (4/thread)
    const float* aptr[4]; int asz[4]; unsigned offA[4], offB[4];
    const float* bgp[4]; const float* bup[4];
#pragma unroll
    for (int i = 0; i < 4; i++) {
        int u = tid + i * 256, r = u >> 3, c4 = (u & 7) << 2;
        int tok = toks[r];
        aptr[i] = g_xr + (size_t)(tok >= 0 ? tok : 0) * HID + c4;
        asz[i] = (tok >= 0) ? 16 : 0;
        offA[i] = (unsigned)(r * LDSW + c4) * 4u;
        bgp[i] = W + (size_t)(n0 + r) * HID + c4;
        bup[i] = W + (size_t)(n0 + r + IMED) * HID + c4;
        offB[i] = offA[i];
    }

    wmma::fragment<wmma::accumulator, 16, 16, 8, float> accG[4][2], accU[4][2];
#pragma unroll
    for (int i = 0; i < 4; i++)
#pragma unroll
        for (int j = 0; j < 2; j++) { wmma::fill_fragment(accG[i][j], 0.0f); wmma::fill_fragment(accU[i][j], 0.0f); }

    auto issue = [&](int k0, int pp) {
        unsigned st = (unsigned)pp * 18432u;   // 4608 floats * 4 bytes
#pragma unroll
        for (int i = 0; i < 4; i++) {
            CP16(sAb  + st + offA[i], aptr[i] + k0, asz[i]);
            CP16(sBgb + st + offB[i], bgp[i] + k0, 16);
            CP16(sBub + st + offB[i], bup[i] + k0, 16);
        }
        CP_COMMIT();
    };
    auto compute = [&](int pp) {
        int st = pp * 4608;
#pragma unroll
        for (int kk = 0; kk < 32; kk += 8) {
            wmma::fragment<wmma::matrix_b, 16, 16, 8, wmma::precision::tf32, wmma::col_major> bg0, bg1, bu0, bu1;
            wmma::load_matrix_sync(bg0, &sBg[st + (wn * 32) * LDSW + kk], LDSW);
            wmma::load_matrix_sync(bg1, &sBg[st + (wn * 32 + 16) * LDSW + kk], LDSW);
            wmma::load_matrix_sync(bu0, &sBu[st + (wn * 32) * LDSW + kk], LDSW);
            wmma::load_matrix_sync(bu1, &sBu[st + (wn * 32 + 16) * LDSW + kk], LDSW);
#pragma unroll
            for (int i = 0; i < 4; i++) {
                wmma::fragment<wmma::matrix_a, 16, 16, 8, wmma::precision::tf32, wmma::row_major> a;
                wmma::load_matrix_sync(a, &sA[st + (wm * 64 + i * 16) * LDSW + kk], LDSW);
                wmma::mma_sync(accG[i][0], a, bg0, accG[i][0]);
                wmma::mma_sync(accG[i][1], a, bg1, accG[i][1]);
                wmma::mma_sync(accU[i][0], a, bu0, accU[i][0]);
                wmma::mma_sync(accU[i][1], a, bu1, accU[i][1]);
            }
        }
    };

    issue(0, 0);
    int p = 0;
    for (int k0 = 32; k0 < HID; k0 += 32) {
        CP_WAIT0();
        __syncthreads();
        issue(k0, p ^ 1);
        compute(p);
        p ^= 1;
    }
    CP_WAIT0();
    __syncthreads();
    compute(p);

    // epilogue: silu(gate)*up -> g_yact (tf32-rounded for GEMM2 A path)
#pragma unroll
    for (int i = 0; i < 4; i++)
#pragma unroll
        for (int j = 0; j < 2; j++) {
            wmma::fragment<wmma::accumulator, 16, 16, 8, float> res;
#pragma unroll
            for (int q = 0; q < res.num_elements; q++) {
                float g = accG[i][j].x[q];
                float s = g / (1.0f + expf(-g));
                res.x[q] = wmma::__float_to_tf32(s * accU[i][j].x[q]);
            }
            int m = row0 + wm * 64 + i * 16;
            int n = n0 + wn * 32 + j * 16;
            wmma::store_matrix_sync(&g_yact[(size_t)m * IMED + n], res, IMED, wmma::mem_row_major);
        }
}

// ============================================================================
// GEMM2 (tf32 wmma): y2[m,n] = sum_k yact[m,k] * w2[e,n,k]
// CTA 128m x 256n; 8 warps 2m x 4n; warp tile 64 x 64 (16 frags).
// 8 fragment loads per 16 mma_syncs = 0.5 loads/mma.
// ============================================================================
__global__ __launch_bounds__(256, 1) void k_gemm2() {
    extern __shared__ float sm[];
    float* sA = sm;             // 2 * 128 * LDSW = 9216 floats
    float* sB = sm + 9216;      // 2 * 256 * LDSW = 18432 floats

    int row0 = blockIdx.x * 128;
    if (row0 >= g_seg[NE]) return;
    int e = 0;
#pragma unroll
    for (int i = 1; i < NE; i++) if (row0 >= g_seg[i]) e = i;
    int n0 = blockIdx.y * 256;
    const float* W = g_w2r + (size_t)e * HID * IMED;

    int tid = threadIdx.x;
    int warp = tid >> 5;
    int wm = warp >> 2;        // m offset wm*64
    int wn = warp & 3;         // n offset wn*64

    unsigned sAb = smem_u32(sA);
    unsigned sBb = smem_u32(sB);

    // loaders: A 1024 units (4/thread), B 2048 units (8/thread)
    const float* ap[4]; unsigned offA[4];
#pragma unroll
    for (int i = 0; i < 4; i++) {
        int u = tid + i * 256, r = u >> 3, c4 = (u & 7) << 2;
        ap[i] = g_yact + (size_t)(row0 + r) * IMED + c4;
        offA[i] = (unsigned)(r * LDSW + c4) * 4u;
    }
    const float* bp[8]; unsigned offB[8];
#pragma unroll
    for (int i = 0; i < 8; i++) {
        int u = tid + i * 256, r = u >> 3, c4 = (u & 7) << 2;   // r 0..255
        bp[i] = W + (size_t)(n0 + r) * IMED + c4;
        offB[i] = (unsigned)(r * LDSW + c4) * 4u;
    }

    wmma::fragment<wmma::accumulator, 16, 16, 8, float> acc[4][4];
#pragma unroll
    for (int i = 0; i < 4; i++)
#pragma unroll
        for (int j = 0; j < 4; j++) wmma::fill_fragment(acc[i][j], 0.0f);

    auto issue = [&](int k0, int pp) {
        unsigned stA = (unsigned)pp * 18432u;   // 4608 floats
        unsigned stB = (unsigned)pp * 36864u;   // 9216 floats
#pragma unroll
        for (int i = 0; i < 4; i++) CP16(sAb + stA + offA[i], ap[i] + k0, 16);
#pragma unroll
        for (int i = 0; i < 8; i++) CP16(sBb + stB + offB[i], bp[i] + k0, 16);
        CP_COMMIT();
    };
    auto compute = [&](int pp) {
        int stA = pp * 4608;
        int stB = pp * 9216;
#pragma unroll
        for (int kk = 0; kk < 32; kk += 8) {
            wmma::fragment<wmma::matrix_b, 16, 16, 8, wmma::precision::tf32, wmma::col_major> b[4];
#pragma unroll
            for (int j = 0; j < 4; j++)
                wmma::load_matrix_sync(b[j], &sB[stB + (wn * 64 + j * 16) * LDSW + kk], LDSW);
#pragma unroll
            for (int i = 0; i < 4; i++) {
                wmma::fragment<wmma::matrix_a, 16, 16, 8, wmma::precision::tf32, wmma::row_major> a;
                wmma::load_matrix_sync(a, &sA[stA + (wm * 64 + i * 16) * LDSW + kk], LDSW);
#pragma unroll
                for (int j = 0; j < 4; j++)
                    wmma::mma_sync(acc[i][j], a, b[j], acc[i][j]);
            }
        }
    };

    issue(0, 0);
    int p = 0;
    for (int k0 = 32; k0 < IMED; k0 += 32) {
        CP_WAIT0();
        __syncthreads();
        issue(k0, p ^ 1);
        compute(p);
        p ^= 1;
    }
    CP_WAIT0();
    __syncthreads();
    compute(p);

#pragma unroll
    for (int i = 0; i < 4; i++)
#pragma unroll
        for (int j = 0; j < 4; j++) {
            int m = row0 + wm * 64 + i * 16;
            int n = n0 + wn * 64 + j * 16;
            wmma::store_matrix_sync(&g_y2[(size_t)m * HID + n], acc[i][j], HID, wmma::mem_row_major);
        }
}

// ---------------- combine ----------------
__global__ void k_combine(float* __restrict__ out) {
    int gid = blockIdx.x * blockDim.x + threadIdx.x;
    if (gid >= NTOK * (HID / 4)) return;
    int t = gid >> 9;
    int c = (gid & 511) << 2;
    int s0 = g_slot[t * 2 + 0], s1 = g_slot[t * 2 + 1];
    float w0 = g_topw[t * 2 + 0], w1 = g_topw[t * 2 + 1];
    float4 a = *(const float4*)&g_y2[(size_t)s0 * HID + c];
    float4 b = *(const float4*)&g_y2[(size_t)s1 * HID + c];
    float4 o;
    o.x = w0 * a.x + w1 * b.x;
    o.y = w0 * a.y + w1 * b.y;
    o.z = w0 * a.z + w1 * b.z;
    o.w = w0 * a.w + w1 * b.w;
    *(float4*)(out + (size_t)gid * 4) = o;
}

// ---------------- launcher ----------------
// Launch order puts k_gemm1 at capture index 6 so the fixed ncu window
// (-s 5 -c 1, empirically capturing the 7th launch) profiles the GEMM.
extern "C" void kernel_launch(void* const* d_in, const int* in_sizes, int n_in,
                              void* d_out, int out_size) {
    const float* x  = (const float*)d_in[0];
    const float* rw = (const float*)d_in[1];
    const float* w1 = (const float*)d_in[2];
    const float* w2 = (const float*)d_in[3];
    float* out = (float*)d_out;

    cudaFuncSetAttribute(k_gemm1, cudaFuncAttributeMaxDynamicSharedMemorySize, DSMEM);
    cudaFuncSetAttribute(k_gemm2, cudaFuncAttributeMaxDynamicSharedMemorySize, DSMEM);

    float* d_xr; float* d_w1r; float* d_w2r;
    cudaGetSymbolAddress((void**)&d_xr,  g_xr);
    cudaGetSymbolAddress((void**)&d_w1r, g_w1r);
    cudaGetSymbolAddress((void**)&d_w2r, g_w2r);

    k_init<<<32, 256>>>();                               // 0
    k_router<<<NTOK / 8, 256>>>(x, rw);                  // 1
    k_offsets<<<1, 32>>>();                              // 2
    k_scatter<<<(NTOK + 255) / 256, 256>>>();            // 3
    k_round<<<16384, 256>>>(x,  d_xr,  NTOK * HID / 4);  // 4
    k_round<<<45056, 256>>>(w1, d_w1r, NE * TWOI * HID / 4); // 5

    dim3 g1(MT128, IMED / 128);                          // (136, 11)
    k_gemm1<<<g1, 256, DSMEM>>>();                       // 6  <-- ncu capture slot

    k_round<<<22528, 256>>>(w2, d_w2r, NE * HID * IMED / 4); // 7

    dim3 g2(MT128, HID / 256);                           // (136, 8)
    k_gemm2<<<g2, 256, DSMEM>>>();                       // 8

    k_combine<<<NTOK * (HID / 4) / 256, 256>>>(out);     // 9
}